// round 1
// baseline (speedup 1.0000x reference)
#include <cuda_runtime.h>
#include <math.h>

#define DMODEL 1024
#define NHEADS 16
#define DK     64
#define SEQ    2048
#define BATCH  2
#define MTOT   (BATCH*SEQ)   // 4096

// Scratch (allocation-free rule: __device__ globals)
__device__ float g_q[MTOT*DMODEL];
__device__ float g_k[MTOT*DMODEL];
__device__ float g_v[MTOT*DMODEL];
__device__ float g_attn[MTOT*DMODEL];

// ---------------------------------------------------------------------------
// SGEMM body: C[M,N] = A[M,K] * W[N,K]^T   (both row-major, K-major rows)
// BM=BN=128, BK=8, 256 threads, 8x8 micro-tile (split 4+4 in each dim)
// ---------------------------------------------------------------------------
#define BM 128
#define BN 128
#define BK 8

__device__ __forceinline__ void gemm_body(const float* __restrict__ A,
                                          const float* __restrict__ W,
                                          float* __restrict__ C,
                                          int M, int N, int K)
{
    __shared__ float As[BK][BM + 4];
    __shared__ float Ws[BK][BN + 4];

    const int tid = threadIdx.x;          // 0..255
    const int tx  = tid & 15;
    const int ty  = tid >> 4;
    const int row0 = blockIdx.y * BM;
    const int col0 = blockIdx.x * BN;

    const int lr = tid >> 1;              // 0..127
    const int lc = (tid & 1) * 4;         // 0 or 4

    const float* Aptr = A + (size_t)(row0 + lr) * K + lc;
    const float* Wptr = W + (size_t)(col0 + lr) * K + lc;

    float acc[8][8];
#pragma unroll
    for (int i = 0; i < 8; i++)
#pragma unroll
        for (int j = 0; j < 8; j++) acc[i][j] = 0.0f;

    for (int k0 = 0; k0 < K; k0 += BK) {
        float4 va = *(const float4*)(Aptr + k0);
        float4 vw = *(const float4*)(Wptr + k0);
        __syncthreads();
        As[lc + 0][lr] = va.x; As[lc + 1][lr] = va.y;
        As[lc + 2][lr] = va.z; As[lc + 3][lr] = va.w;
        Ws[lc + 0][lr] = vw.x; Ws[lc + 1][lr] = vw.y;
        Ws[lc + 2][lr] = vw.z; Ws[lc + 3][lr] = vw.w;
        __syncthreads();

#pragma unroll
        for (int kk = 0; kk < BK; kk++) {
            float a[8], b[8];
            *(float4*)&a[0] = *(const float4*)&As[kk][ty * 4];
            *(float4*)&a[4] = *(const float4*)&As[kk][64 + ty * 4];
            *(float4*)&b[0] = *(const float4*)&Ws[kk][tx * 4];
            *(float4*)&b[4] = *(const float4*)&Ws[kk][64 + tx * 4];
#pragma unroll
            for (int i = 0; i < 8; i++)
#pragma unroll
                for (int j = 0; j < 8; j++)
                    acc[i][j] = fmaf(a[i], b[j], acc[i][j]);
        }
    }

#pragma unroll
    for (int i = 0; i < 8; i++) {
        int r = row0 + ((i < 4) ? (ty * 4 + i) : (64 + ty * 4 + i - 4));
        float4 v0 = make_float4(acc[i][0], acc[i][1], acc[i][2], acc[i][3]);
        float4 v1 = make_float4(acc[i][4], acc[i][5], acc[i][6], acc[i][7]);
        *(float4*)&C[(size_t)r * N + col0 + tx * 4]      = v0;
        *(float4*)&C[(size_t)r * N + col0 + 64 + tx * 4] = v1;
    }
}

// QKV fused: grid.z in {0,1,2} selects weight+destination
__global__ __launch_bounds__(256, 2)
void qkv_kernel(const float* __restrict__ x,
                const float* __restrict__ wq,
                const float* __restrict__ wk,
                const float* __restrict__ wv)
{
    const float* W = (blockIdx.z == 0) ? wq : (blockIdx.z == 1) ? wk : wv;
    float* C       = (blockIdx.z == 0) ? g_q : (blockIdx.z == 1) ? g_k : g_v;
    gemm_body(x, W, C, MTOT, DMODEL, DMODEL);
}

// Output projection: out = g_attn @ o_proj^T
__global__ __launch_bounds__(256, 2)
void oproj_kernel(const float* __restrict__ wo, float* __restrict__ out)
{
    gemm_body(g_attn, wo, out, MTOT, DMODEL, DMODEL);
}

// ---------------------------------------------------------------------------
// Flash attention (fp32, causal). Block = 256 threads handles 64 query rows
// for one (b,h). Key tiles of 64, online softmax.
// smem: Qs[64][65], Ks[64][65], Vs[64][64], Ps[64][65]  -> 66304 bytes dynamic
// ---------------------------------------------------------------------------
#define QPAD 65
#define ATTN_SMEM_BYTES ((64*QPAD + 64*QPAD + 64*64 + 64*QPAD) * 4)

__global__ __launch_bounds__(256, 1)
void attn_kernel()
{
    extern __shared__ float sm[];
    float* Qs = sm;                      // 64 x 65
    float* Ks = Qs + 64 * QPAD;          // 64 x 65
    float* Vs = Ks + 64 * QPAD;          // 64 x 64
    float* Ps = Vs + 64 * 64;            // 64 x 65

    const int qt = blockIdx.x;           // query tile 0..31
    const int bh = blockIdx.y;           // 0..31
    const int b  = bh >> 4;
    const int h  = bh & 15;

    const float* Qg = g_q + (size_t)b * SEQ * DMODEL + h * DK;
    const float* Kg = g_k + (size_t)b * SEQ * DMODEL + h * DK;
    const float* Vg = g_v + (size_t)b * SEQ * DMODEL + h * DK;

    const int tid = threadIdx.x;
    const int tx  = tid & 15;
    const int ty  = tid >> 4;

    // Load Q tile (64 rows x 64), strided global rows of DMODEL
    for (int i = tid; i < 64 * 16; i += 256) {
        int row = i >> 4, seg = (i & 15) * 4;
        float4 v = *(const float4*)&Qg[(size_t)(qt * 64 + row) * DMODEL + seg];
        Qs[row * QPAD + seg + 0] = v.x; Qs[row * QPAD + seg + 1] = v.y;
        Qs[row * QPAD + seg + 2] = v.z; Qs[row * QPAD + seg + 3] = v.w;
    }

    float m[4], l[4], acc[4][4];
#pragma unroll
    for (int i = 0; i < 4; i++) {
        m[i] = -1e30f; l[i] = 0.0f;
#pragma unroll
        for (int j = 0; j < 4; j++) acc[i][j] = 0.0f;
    }

    for (int jt = 0; jt <= qt; jt++) {
        __syncthreads();   // protects Qs (iter 0) and Ps/Vs/Ks of prev iter
        // Load K,V tiles
        for (int i = tid; i < 64 * 16; i += 256) {
            int row = i >> 4, seg = (i & 15) * 4;
            size_t goff = (size_t)(jt * 64 + row) * DMODEL + seg;
            float4 kv = *(const float4*)&Kg[goff];
            Ks[row * QPAD + seg + 0] = kv.x; Ks[row * QPAD + seg + 1] = kv.y;
            Ks[row * QPAD + seg + 2] = kv.z; Ks[row * QPAD + seg + 3] = kv.w;
            float4 vv = *(const float4*)&Vg[goff];
            *(float4*)&Vs[row * 64 + seg] = vv;
        }
        __syncthreads();

        // S = Q K^T * 1/sqrt(dk)
        float s[4][4];
#pragma unroll
        for (int i = 0; i < 4; i++)
#pragma unroll
            for (int j = 0; j < 4; j++) s[i][j] = 0.0f;

#pragma unroll 4
        for (int kk = 0; kk < 64; kk++) {
            float a[4], bb[4];
#pragma unroll
            for (int i = 0; i < 4; i++) a[i]  = Qs[(ty * 4 + i) * QPAD + kk];
#pragma unroll
            for (int j = 0; j < 4; j++) bb[j] = Ks[(tx * 4 + j) * QPAD + kk];
#pragma unroll
            for (int i = 0; i < 4; i++)
#pragma unroll
                for (int j = 0; j < 4; j++)
                    s[i][j] = fmaf(a[i], bb[j], s[i][j]);
        }

        const bool diag = (jt == qt);
#pragma unroll
        for (int i = 0; i < 4; i++) {
            int qrow = qt * 64 + ty * 4 + i;
#pragma unroll
            for (int j = 0; j < 4; j++) {
                int key = jt * 64 + tx * 4 + j;
                s[i][j] *= 0.125f;
                if (diag && key > qrow) s[i][j] = -1e30f;
            }
        }

        // Online softmax update
#pragma unroll
        for (int i = 0; i < 4; i++) {
            float mx = s[i][0];
#pragma unroll
            for (int j = 1; j < 4; j++) mx = fmaxf(mx, s[i][j]);
#pragma unroll
            for (int o = 8; o >= 1; o >>= 1)
                mx = fmaxf(mx, __shfl_xor_sync(0xffffffffu, mx, o));
            float newm = fmaxf(m[i], mx);
            float scale = __expf(m[i] - newm);
            float rs = 0.0f;
#pragma unroll
            for (int j = 0; j < 4; j++) {
                float p = __expf(s[i][j] - newm);
                s[i][j] = p;
                rs += p;
            }
#pragma unroll
            for (int o = 8; o >= 1; o >>= 1)
                rs += __shfl_xor_sync(0xffffffffu, rs, o);
            l[i] = l[i] * scale + rs;
            m[i] = newm;
#pragma unroll
            for (int j = 0; j < 4; j++) acc[i][j] *= scale;
            // stage P
#pragma unroll
            for (int j = 0; j < 4; j++)
                Ps[(ty * 4 + i) * QPAD + tx * 4 + j] = s[i][j];
        }
        __syncthreads();

        // O += P @ V
#pragma unroll 4
        for (int kkey = 0; kkey < 64; kkey++) {
            float pa[4], vb[4];
#pragma unroll
            for (int i = 0; i < 4; i++) pa[i] = Ps[(ty * 4 + i) * QPAD + kkey];
#pragma unroll
            for (int j = 0; j < 4; j++) vb[j] = Vs[kkey * 64 + tx * 4 + j];
#pragma unroll
            for (int i = 0; i < 4; i++)
#pragma unroll
                for (int j = 0; j < 4; j++)
                    acc[i][j] = fmaf(pa[i], vb[j], acc[i][j]);
        }
    }

    // Write normalized output to g_attn[b, s, h, d]
    float* Og = g_attn + (size_t)b * SEQ * DMODEL + h * DK;
#pragma unroll
    for (int i = 0; i < 4; i++) {
        float inv = 1.0f / l[i];
        int row = qt * 64 + ty * 4 + i;
        float4 v = make_float4(acc[i][0] * inv, acc[i][1] * inv,
                               acc[i][2] * inv, acc[i][3] * inv);
        *(float4*)&Og[(size_t)row * DMODEL + tx * 4] = v;
    }
}

// ---------------------------------------------------------------------------
extern "C" void kernel_launch(void* const* d_in, const int* in_sizes, int n_in,
                              void* d_out, int out_size)
{
    (void)in_sizes; (void)n_in; (void)out_size;
    const float* x  = (const float*)d_in[0];
    const float* wq = (const float*)d_in[1];
    const float* wk = (const float*)d_in[2];
    const float* wv = (const float*)d_in[3];
    const float* wo = (const float*)d_in[4];
    float* out = (float*)d_out;

    static bool attr_set = false;
    if (!attr_set) {
        cudaFuncSetAttribute(attn_kernel,
                             cudaFuncAttributeMaxDynamicSharedMemorySize,
                             ATTN_SMEM_BYTES);
        attr_set = true;
    }

    dim3 gemm_grid(DMODEL / BN, MTOT / BM);      // (8, 32)
    dim3 qkv_grid(DMODEL / BN, MTOT / BM, 3);    // (8, 32, 3)

    qkv_kernel<<<qkv_grid, 256>>>(x, wq, wk, wv);
    attn_kernel<<<dim3(SEQ / 64, BATCH * NHEADS), 256, ATTN_SMEM_BYTES>>>();
    oproj_kernel<<<gemm_grid, 256>>>(wo, out);
}

// round 3
// speedup vs baseline: 1.5530x; 1.5530x over previous
#include <cuda_runtime.h>
#include <cuda_bf16.h>
#include <cstdint>
#include <math.h>

#define DMODEL 1024
#define NHEADS 16
#define DK     64
#define SEQ    2048
#define BATCH  2
#define MTOT   (BATCH*SEQ)   // 4096

// Scratch (allocation-free rule: __device__ globals)
__device__ float g_q[MTOT*DMODEL];
__device__ float g_k[MTOT*DMODEL];
__device__ float g_v[MTOT*DMODEL];
__device__ float g_attn[MTOT*DMODEL];

// ============================================================================
// bf16-split GEMM via mma.sync (legal on plain sm_100 target).
// C[M,N] = A[M,K] * W[N,K]^T ; CTA tile 128x128, BK=32, 8 warps (4x2),
// warp tile 32(m) x 64(n). 3 passes: Ah*Bh + Al*Bh + Ah*Bl.
// ============================================================================
#define BK 32
#define RS 40   // bf16 elements per smem row (32 + 8 pad) -> 80B row stride

static __device__ __forceinline__ void mma_bf16(float* c, const uint32_t* a,
                                                const uint32_t* b) {
    asm volatile(
        "mma.sync.aligned.m16n8k16.row.col.f32.bf16.bf16.f32 "
        "{%0,%1,%2,%3}, {%4,%5,%6,%7}, {%8,%9}, {%0,%1,%2,%3};"
        : "+f"(c[0]), "+f"(c[1]), "+f"(c[2]), "+f"(c[3])
        : "r"(a[0]), "r"(a[1]), "r"(a[2]), "r"(a[3]), "r"(b[0]), "r"(b[1]));
}

static __device__ __forceinline__ uint32_t pack2(__nv_bfloat16 x, __nv_bfloat16 y) {
    __nv_bfloat162 t(x, y);
    return *(uint32_t*)&t;
}

static __device__ __forceinline__ void split4(float4 v, uint2& hi, uint2& lo) {
    __nv_bfloat16 hx = __float2bfloat16_rn(v.x);
    __nv_bfloat16 hy = __float2bfloat16_rn(v.y);
    __nv_bfloat16 hz = __float2bfloat16_rn(v.z);
    __nv_bfloat16 hw = __float2bfloat16_rn(v.w);
    hi.x = pack2(hx, hy);
    hi.y = pack2(hz, hw);
    lo.x = pack2(__float2bfloat16_rn(v.x - __bfloat162float(hx)),
                 __float2bfloat16_rn(v.y - __bfloat162float(hy)));
    lo.y = pack2(__float2bfloat16_rn(v.z - __bfloat162float(hz)),
                 __float2bfloat16_rn(v.w - __bfloat162float(hw)));
}

static __device__ __forceinline__ void gemm_body(const float* __restrict__ A,
                                                 const float* __restrict__ W,
                                                 float* __restrict__ C)
{
    __shared__ __align__(16) uint16_t Ah[128 * RS];
    __shared__ __align__(16) uint16_t Al[128 * RS];
    __shared__ __align__(16) uint16_t Bh[128 * RS];
    __shared__ __align__(16) uint16_t Bl[128 * RS];

    const int tid  = threadIdx.x;
    const int lane = tid & 31;
    const int warp = tid >> 5;
    const int wy = warp >> 1;           // 0..3 -> m offset wy*32
    const int wx = warp & 1;            // 0..1 -> n offset wx*64
    const int gi = lane >> 2;           // 0..7
    const int tg = lane & 3;            // 0..3

    const int row0 = blockIdx.y * 128;
    const int col0 = blockIdx.x * 128;

    const int ldrow = tid >> 3;         // 0..31 ... with u: rows 0..127
    const int ldseg = tid & 7;          // float4 segment within 32 floats

    float acc[2][8][4];
#pragma unroll
    for (int mt = 0; mt < 2; mt++)
#pragma unroll
        for (int nt = 0; nt < 8; nt++)
#pragma unroll
            for (int r = 0; r < 4; r++) acc[mt][nt][r] = 0.0f;

    float4 av[4], bv[4];
    // prologue: chunk 0
#pragma unroll
    for (int u = 0; u < 4; u++) {
        int row = ldrow + u * 32;
        av[u] = *(const float4*)&A[(size_t)(row0 + row) * 1024 + ldseg * 4];
        bv[u] = *(const float4*)&W[(size_t)(col0 + row) * 1024 + ldseg * 4];
    }
#pragma unroll
    for (int u = 0; u < 4; u++) {
        int row = ldrow + u * 32;
        uint2 h, l;
        split4(av[u], h, l);
        *(uint2*)&Ah[row * RS + ldseg * 4] = h;
        *(uint2*)&Al[row * RS + ldseg * 4] = l;
        split4(bv[u], h, l);
        *(uint2*)&Bh[row * RS + ldseg * 4] = h;
        *(uint2*)&Bl[row * RS + ldseg * 4] = l;
    }
    __syncthreads();

    for (int kc = 0; kc < 32; kc++) {
        // prefetch next chunk from gmem
        if (kc < 31) {
#pragma unroll
            for (int u = 0; u < 4; u++) {
                int row = ldrow + u * 32;
                av[u] = *(const float4*)&A[(size_t)(row0 + row) * 1024 + (kc + 1) * 32 + ldseg * 4];
                bv[u] = *(const float4*)&W[(size_t)(col0 + row) * 1024 + (kc + 1) * 32 + ldseg * 4];
            }
        }

        // compute current chunk: 2 k16-steps
#pragma unroll
        for (int ks = 0; ks < 2; ks++) {
            uint32_t afh[2][4], afl[2][4], bfh[8][2], bfl[8][2];
#pragma unroll
            for (int mt = 0; mt < 2; mt++) {
                int r = wy * 32 + mt * 16 + gi;
                int cbase = ks * 16 + 2 * tg;
                afh[mt][0] = *(const uint32_t*)&Ah[r * RS + cbase];
                afh[mt][1] = *(const uint32_t*)&Ah[(r + 8) * RS + cbase];
                afh[mt][2] = *(const uint32_t*)&Ah[r * RS + cbase + 8];
                afh[mt][3] = *(const uint32_t*)&Ah[(r + 8) * RS + cbase + 8];
                afl[mt][0] = *(const uint32_t*)&Al[r * RS + cbase];
                afl[mt][1] = *(const uint32_t*)&Al[(r + 8) * RS + cbase];
                afl[mt][2] = *(const uint32_t*)&Al[r * RS + cbase + 8];
                afl[mt][3] = *(const uint32_t*)&Al[(r + 8) * RS + cbase + 8];
            }
#pragma unroll
            for (int nt = 0; nt < 8; nt++) {
                int c = wx * 64 + nt * 8 + gi;
                int cbase = ks * 16 + 2 * tg;
                bfh[nt][0] = *(const uint32_t*)&Bh[c * RS + cbase];
                bfh[nt][1] = *(const uint32_t*)&Bh[c * RS + cbase + 8];
                bfl[nt][0] = *(const uint32_t*)&Bl[c * RS + cbase];
                bfl[nt][1] = *(const uint32_t*)&Bl[c * RS + cbase + 8];
            }
#pragma unroll
            for (int mt = 0; mt < 2; mt++)
#pragma unroll
                for (int nt = 0; nt < 8; nt++) {
                    mma_bf16(acc[mt][nt], afh[mt], bfh[nt]);
                    mma_bf16(acc[mt][nt], afl[mt], bfh[nt]);
                    mma_bf16(acc[mt][nt], afh[mt], bfl[nt]);
                }
        }
        __syncthreads();

        if (kc < 31) {
#pragma unroll
            for (int u = 0; u < 4; u++) {
                int row = ldrow + u * 32;
                uint2 h, l;
                split4(av[u], h, l);
                *(uint2*)&Ah[row * RS + ldseg * 4] = h;
                *(uint2*)&Al[row * RS + ldseg * 4] = l;
                split4(bv[u], h, l);
                *(uint2*)&Bh[row * RS + ldseg * 4] = h;
                *(uint2*)&Bl[row * RS + ldseg * 4] = l;
            }
            __syncthreads();
        }
    }

    // write-out: per mma tile, c0/c1 at row gi, c2/c3 at row gi+8, cols 2*tg
#pragma unroll
    for (int mt = 0; mt < 2; mt++) {
        int rbase = row0 + wy * 32 + mt * 16;
#pragma unroll
        for (int nt = 0; nt < 8; nt++) {
            int c = col0 + wx * 64 + nt * 8 + 2 * tg;
            *(float2*)&C[(size_t)(rbase + gi) * 1024 + c] =
                make_float2(acc[mt][nt][0], acc[mt][nt][1]);
            *(float2*)&C[(size_t)(rbase + gi + 8) * 1024 + c] =
                make_float2(acc[mt][nt][2], acc[mt][nt][3]);
        }
    }
}

__global__ void __launch_bounds__(256, 1)
proj_kernel(const float* __restrict__ x,
            const float* __restrict__ wq,
            const float* __restrict__ wk,
            const float* __restrict__ wv)
{
    const float* W = (blockIdx.z == 0) ? wq : (blockIdx.z == 1) ? wk : wv;
    float* C       = (blockIdx.z == 0) ? g_q : (blockIdx.z == 1) ? g_k : g_v;
    gemm_body(x, W, C);
}

__global__ void __launch_bounds__(256, 1)
oproj_kernel(const float* __restrict__ wo, float* __restrict__ out)
{
    gemm_body(g_attn, wo, out);
}

// ============================================================================
// Flash attention (fp32, causal). 128 q-rows/CTA, 128-key tiles, 256 threads.
// S micro-tile 8x8 (ty rows, tx key-cols); O micro-tile 8x4 (tx dk-cols).
// K stored transposed in smem for conflict-free float4 b-loads.
// ============================================================================
#define QP 68
#define KP 132
#define VP 68
#define PP 132
#define OFF_Q 0
#define OFF_K (128*QP)
#define OFF_V (OFF_K + 64*KP)
#define OFF_P (OFF_V + 128*VP)
#define ATTN_FLOATS (OFF_P + 128*PP)
#define ATTN_BYTES (ATTN_FLOATS*4)        // 171008

__global__ void __launch_bounds__(256, 1)
attn_kernel()
{
    extern __shared__ float sm[];
    float* Qs = sm + OFF_Q;   // [128][QP] row-major (q rows x dk)
    float* Kt = sm + OFF_K;   // [64][KP]  transposed (dk x keys)
    float* Vs = sm + OFF_V;   // [128][VP] row-major (keys x dk)
    float* Ps = sm + OFF_P;   // [128][PP] row-major (q rows x keys)

    const int qt = blockIdx.x;          // 0..15
    const int bh = blockIdx.y;          // 0..31
    const int b  = bh >> 4;
    const int h  = bh & 15;

    const float* Qg = g_q + (size_t)b * SEQ * DMODEL + h * DK;
    const float* Kg = g_k + (size_t)b * SEQ * DMODEL + h * DK;
    const float* Vg = g_v + (size_t)b * SEQ * DMODEL + h * DK;

    const int tid = threadIdx.x;
    const int tx  = tid & 15;
    const int ty  = tid >> 4;

    // Load Q tile (128 rows x 64)
#pragma unroll
    for (int u = 0; u < 8; u++) {
        int f = tid + u * 256;
        int row = f >> 4, seg = f & 15;
        float4 v = *(const float4*)&Qg[(size_t)(qt * 128 + row) * DMODEL + seg * 4];
        *(float4*)&Qs[row * QP + seg * 4] = v;
    }

    float m[8], l[8], acc[8][4];
#pragma unroll
    for (int i = 0; i < 8; i++) {
        m[i] = -1e30f; l[i] = 0.0f;
#pragma unroll
        for (int j = 0; j < 4; j++) acc[i][j] = 0.0f;
    }

    for (int jt = 0; jt <= qt; jt++) {
        __syncthreads();   // protect Qs (iter0) and Kt/Vs/Ps of prev iter
        // load K (transposed) and V (natural)
#pragma unroll
        for (int u = 0; u < 8; u++) {
            int f = tid + u * 256;
            int row = f >> 4, seg = f & 15;
            size_t go = (size_t)(jt * 128 + row) * DMODEL + seg * 4;
            float4 kv = *(const float4*)&Kg[go];
            int col = seg * 4;
            Kt[(col + 0) * KP + row] = kv.x;
            Kt[(col + 1) * KP + row] = kv.y;
            Kt[(col + 2) * KP + row] = kv.z;
            Kt[(col + 3) * KP + row] = kv.w;
            *(float4*)&Vs[row * VP + col] = *(const float4*)&Vg[go];
        }
        __syncthreads();

        // S = Q K^T (8x8 per thread)
        float s[8][8];
#pragma unroll
        for (int i = 0; i < 8; i++)
#pragma unroll
            for (int j = 0; j < 8; j++) s[i][j] = 0.0f;

#pragma unroll 4
        for (int kk = 0; kk < 64; kk++) {
            float a[8], bb[8];
#pragma unroll
            for (int i = 0; i < 8; i++) a[i] = Qs[(ty * 8 + i) * QP + kk];
            *(float4*)&bb[0] = *(const float4*)&Kt[kk * KP + tx * 8];
            *(float4*)&bb[4] = *(const float4*)&Kt[kk * KP + tx * 8 + 4];
#pragma unroll
            for (int i = 0; i < 8; i++)
#pragma unroll
                for (int j = 0; j < 8; j++)
                    s[i][j] = fmaf(a[i], bb[j], s[i][j]);
        }

        const bool diag = (jt == qt);
#pragma unroll
        for (int i = 0; i < 8; i++) {
            int qrow = qt * 128 + ty * 8 + i;
#pragma unroll
            for (int j = 0; j < 8; j++) {
                int key = jt * 128 + tx * 8 + j;
                s[i][j] *= 0.125f;
                if (diag && key > qrow) s[i][j] = -1e30f;
            }
        }

        // online softmax (row reduction across 16 tx lanes)
#pragma unroll
        for (int i = 0; i < 8; i++) {
            float mx = s[i][0];
#pragma unroll
            for (int j = 1; j < 8; j++) mx = fmaxf(mx, s[i][j]);
#pragma unroll
            for (int o = 8; o >= 1; o >>= 1)
                mx = fmaxf(mx, __shfl_xor_sync(0xffffffffu, mx, o));
            float newm = fmaxf(m[i], mx);
            float sc = __expf(m[i] - newm);
            float rs = 0.0f;
#pragma unroll
            for (int j = 0; j < 8; j++) {
                float p = __expf(s[i][j] - newm);
                s[i][j] = p;
                rs += p;
            }
#pragma unroll
            for (int o = 8; o >= 1; o >>= 1)
                rs += __shfl_xor_sync(0xffffffffu, rs, o);
            l[i] = l[i] * sc + rs;
            m[i] = newm;
#pragma unroll
            for (int j = 0; j < 4; j++) acc[i][j] *= sc;
            *(float4*)&Ps[(ty * 8 + i) * PP + tx * 8]     =
                make_float4(s[i][0], s[i][1], s[i][2], s[i][3]);
            *(float4*)&Ps[(ty * 8 + i) * PP + tx * 8 + 4] =
                make_float4(s[i][4], s[i][5], s[i][6], s[i][7]);
        }
        __syncthreads();

        // O += P @ V  (8 rows x 4 dk-cols per thread)
#pragma unroll 4
        for (int kkey = 0; kkey < 128; kkey++) {
            float pa[8];
#pragma unroll
            for (int i = 0; i < 8; i++) pa[i] = Ps[(ty * 8 + i) * PP + kkey];
            float4 vb = *(const float4*)&Vs[kkey * VP + tx * 4];
#pragma unroll
            for (int i = 0; i < 8; i++) {
                acc[i][0] = fmaf(pa[i], vb.x, acc[i][0]);
                acc[i][1] = fmaf(pa[i], vb.y, acc[i][1]);
                acc[i][2] = fmaf(pa[i], vb.z, acc[i][2]);
                acc[i][3] = fmaf(pa[i], vb.w, acc[i][3]);
            }
        }
    }

    // write O
    float* Og = g_attn + (size_t)b * SEQ * DMODEL + h * DK;
#pragma unroll
    for (int i = 0; i < 8; i++) {
        float inv = 1.0f / l[i];
        int row = qt * 128 + ty * 8 + i;
        *(float4*)&Og[(size_t)row * DMODEL + tx * 4] =
            make_float4(acc[i][0] * inv, acc[i][1] * inv,
                        acc[i][2] * inv, acc[i][3] * inv);
    }
}

// ============================================================================
extern "C" void kernel_launch(void* const* d_in, const int* in_sizes, int n_in,
                              void* d_out, int out_size)
{
    (void)in_sizes; (void)n_in; (void)out_size;
    const float* x  = (const float*)d_in[0];
    const float* wq = (const float*)d_in[1];
    const float* wk = (const float*)d_in[2];
    const float* wv = (const float*)d_in[3];
    const float* wo = (const float*)d_in[4];
    float* out = (float*)d_out;

    cudaFuncSetAttribute(attn_kernel,
                         cudaFuncAttributeMaxDynamicSharedMemorySize, ATTN_BYTES);

    proj_kernel<<<dim3(8, 32, 3), 256>>>(x, wq, wk, wv);
    attn_kernel<<<dim3(SEQ / 128, BATCH * NHEADS), 256, ATTN_BYTES>>>();
    oproj_kernel<<<dim3(8, 32), 256>>>(wo, out);
}

// round 5
// speedup vs baseline: 2.6578x; 1.7114x over previous
#include <cuda_runtime.h>
#include <cuda_bf16.h>
#include <cstdint>
#include <math.h>

#define DMODEL 1024
#define NHEADS 16
#define DK     64
#define SEQ    2048
#define BATCH  2
#define MTOT   (BATCH*SEQ)   // 4096

// ---------------------------------------------------------------------------
// Global bf16 scratch (hi/lo split pairs)
// ---------------------------------------------------------------------------
__device__ __nv_bfloat16 g_xh[MTOT*DMODEL], g_xl[MTOT*DMODEL];
__device__ __nv_bfloat16 g_wh[4*DMODEL*DMODEL], g_wl[4*DMODEL*DMODEL];
__device__ __nv_bfloat16 g_qh[MTOT*DMODEL], g_ql[MTOT*DMODEL];
__device__ __nv_bfloat16 g_kh[MTOT*DMODEL], g_kl[MTOT*DMODEL];
__device__ __nv_bfloat16 g_vh[MTOT*DMODEL], g_vl[MTOT*DMODEL];
__device__ __nv_bfloat16 g_ah[MTOT*DMODEL], g_al[MTOT*DMODEL];

// ---------------------------------------------------------------------------
// Helpers
// ---------------------------------------------------------------------------
static __device__ __forceinline__ uint32_t s2u(const void* p) {
    uint32_t a;
    asm("{ .reg .u64 t; cvta.to.shared.u64 t, %1; cvt.u32.u64 %0, t; }"
        : "=r"(a) : "l"(p));
    return a;
}

#define CPA(dst, src) \
    asm volatile("cp.async.cg.shared.global [%0], [%1], 16;" \
                 :: "r"(dst), "l"(__cvta_generic_to_global(src)) : "memory")
#define CPC() asm volatile("cp.async.commit_group;" ::: "memory")
#define CPW(n) asm volatile("cp.async.wait_group %0;" :: "n"(n) : "memory")

static __device__ __forceinline__ void mma_bf16(float* c, const uint32_t* a,
                                                const uint32_t* b) {
    asm volatile(
        "mma.sync.aligned.m16n8k16.row.col.f32.bf16.bf16.f32 "
        "{%0,%1,%2,%3}, {%4,%5,%6,%7}, {%8,%9}, {%0,%1,%2,%3};"
        : "+f"(c[0]), "+f"(c[1]), "+f"(c[2]), "+f"(c[3])
        : "r"(a[0]), "r"(a[1]), "r"(a[2]), "r"(a[3]), "r"(b[0]), "r"(b[1]));
}

static __device__ __forceinline__ void ldmx4t(uint32_t& r0, uint32_t& r1,
                                              uint32_t& r2, uint32_t& r3,
                                              uint32_t a) {
    asm volatile(
        "ldmatrix.sync.aligned.m8n8.x4.trans.shared.b16 {%0,%1,%2,%3}, [%4];"
        : "=r"(r0), "=r"(r1), "=r"(r2), "=r"(r3) : "r"(a));
}

static __device__ __forceinline__ void splitf(float v, __nv_bfloat16& h,
                                              __nv_bfloat16& l) {
    h = __float2bfloat16_rn(v);
    l = __float2bfloat16_rn(v - __bfloat162float(h));
}

static __device__ __forceinline__ uint32_t packbf(__nv_bfloat16 lo, __nv_bfloat16 hi) {
    __nv_bfloat162 t;
    t.x = lo; t.y = hi;
    return *(uint32_t*)&t;
}

// ---------------------------------------------------------------------------
// Split kernel: fp32 -> bf16 hi/lo for x and all 4 weights. 8192 blocks.
// ---------------------------------------------------------------------------
__global__ void __launch_bounds__(256)
split_kernel(const float* __restrict__ x,  const float* __restrict__ wq,
             const float* __restrict__ wk, const float* __restrict__ wv,
             const float* __restrict__ wo)
{
    int bid = blockIdx.x;
    const float4* src;
    uint2 *dh, *dl;
    int idx;
    if (bid < 4096) {
        src = (const float4*)x; dh = (uint2*)g_xh; dl = (uint2*)g_xl; idx = bid;
    } else {
        int t = bid - 4096;
        int w = t >> 10;
        idx = t & 1023;
        const float* ws = (w == 0) ? wq : (w == 1) ? wk : (w == 2) ? wv : wo;
        src = (const float4*)ws;
        dh = (uint2*)(g_wh + ((size_t)w << 20));
        dl = (uint2*)(g_wl + ((size_t)w << 20));
    }
    int i = idx * 256 + threadIdx.x;
    float4 v = src[i];
    __nv_bfloat16 h0, l0, h1, l1, h2, l2, h3, l3;
    splitf(v.x, h0, l0); splitf(v.y, h1, l1);
    splitf(v.z, h2, l2); splitf(v.w, h3, l3);
    dh[i] = make_uint2(packbf(h0, h1), packbf(h2, h3));
    dl[i] = make_uint2(packbf(l0, l1), packbf(l2, l3));
}

// ---------------------------------------------------------------------------
// bf16-split GEMM, pre-split inputs, cp.async double buffer.
// C[M,N] = A[M,K] * W[N,K]^T, CTA 128x128, BK=32, 8 warps (4x2).
// ---------------------------------------------------------------------------
#define RS 40
#define GA_STAGE 10240                   // bytes per array per stage
#define G_STAGE  40960
#define GEMM_SMEM (2*G_STAGE)            // 81920

template<bool SPLIT_OUT>
static __device__ void gemm_core(const __nv_bfloat16* __restrict__ Ah,
                                 const __nv_bfloat16* __restrict__ Al,
                                 const __nv_bfloat16* __restrict__ Bh,
                                 const __nv_bfloat16* __restrict__ Bl,
                                 __nv_bfloat16* __restrict__ Ch,
                                 __nv_bfloat16* __restrict__ Cl,
                                 float* __restrict__ Cf)
{
    extern __shared__ char smem[];
    const uint32_t sb = s2u(smem);
    const int tid  = threadIdx.x;
    const int lane = tid & 31;
    const int warp = tid >> 5;
    const int wy = warp >> 1, wx = warp & 1;
    const int gi = lane >> 2, tg = lane & 3;
    const int row0 = blockIdx.y * 128;
    const int col0 = blockIdx.x * 128;

    float acc[2][8][4];
#pragma unroll
    for (int mt = 0; mt < 2; mt++)
#pragma unroll
        for (int nt = 0; nt < 8; nt++)
#pragma unroll
            for (int r = 0; r < 4; r++) acc[mt][nt][r] = 0.0f;

    // stage loader: 512 chunks per array, 2 per thread per array
#define GEMM_LOAD(kc, s)                                                     \
    {                                                                        \
        uint32_t d0 = sb + (uint32_t)(s) * G_STAGE;                          \
        _Pragma("unroll")                                                    \
        for (int c = 0; c < 2; c++) {                                        \
            int f = tid + c * 256;                                           \
            int row = f >> 2, seg = f & 3;                                   \
            size_t goA = (size_t)(row0 + row) * 1024 + (kc) * 32 + seg * 8;  \
            size_t goB = (size_t)(col0 + row) * 1024 + (kc) * 32 + seg * 8;  \
            uint32_t so = (uint32_t)(row * 80 + seg * 16);                   \
            CPA(d0 + so,                Ah + goA);                           \
            CPA(d0 + GA_STAGE + so,     Al + goA);                           \
            CPA(d0 + 2 * GA_STAGE + so, Bh + goB);                           \
            CPA(d0 + 3 * GA_STAGE + so, Bl + goB);                           \
        }                                                                    \
    }

    GEMM_LOAD(0, 0);
    CPC();

#pragma unroll 1
    for (int kc = 0; kc < 32; kc++) {
        const int s = kc & 1;
        __syncthreads();
        if (kc + 1 < 32) { GEMM_LOAD(kc + 1, s ^ 1); CPC(); CPW(1); }
        else             { CPW(0); }
        __syncthreads();

        const uint16_t* sAh = (const uint16_t*)(smem + s * G_STAGE);
        const uint16_t* sAl = sAh + 5120;
        const uint16_t* sBh = sAh + 10240;
        const uint16_t* sBl = sAh + 15360;

#pragma unroll
        for (int ks = 0; ks < 2; ks++) {
            const int cb = ks * 16 + 2 * tg;
            uint32_t afh[2][4], afl[2][4];
#pragma unroll
            for (int mt = 0; mt < 2; mt++) {
                int r = wy * 32 + mt * 16 + gi;
                afh[mt][0] = *(const uint32_t*)&sAh[r * RS + cb];
                afh[mt][1] = *(const uint32_t*)&sAh[(r + 8) * RS + cb];
                afh[mt][2] = *(const uint32_t*)&sAh[r * RS + cb + 8];
                afh[mt][3] = *(const uint32_t*)&sAh[(r + 8) * RS + cb + 8];
                afl[mt][0] = *(const uint32_t*)&sAl[r * RS + cb];
                afl[mt][1] = *(const uint32_t*)&sAl[(r + 8) * RS + cb];
                afl[mt][2] = *(const uint32_t*)&sAl[r * RS + cb + 8];
                afl[mt][3] = *(const uint32_t*)&sAl[(r + 8) * RS + cb + 8];
            }
#pragma unroll
            for (int nt = 0; nt < 8; nt++) {
                int c = wx * 64 + nt * 8 + gi;
                uint32_t bfh[2], bfl[2];
                bfh[0] = *(const uint32_t*)&sBh[c * RS + cb];
                bfh[1] = *(const uint32_t*)&sBh[c * RS + cb + 8];
                bfl[0] = *(const uint32_t*)&sBl[c * RS + cb];
                bfl[1] = *(const uint32_t*)&sBl[c * RS + cb + 8];
#pragma unroll
                for (int mt = 0; mt < 2; mt++) {
                    mma_bf16(acc[mt][nt], afh[mt], bfh);
                    mma_bf16(acc[mt][nt], afl[mt], bfh);
                    mma_bf16(acc[mt][nt], afh[mt], bfl);
                }
            }
        }
    }

    // epilogue
#pragma unroll
    for (int mt = 0; mt < 2; mt++) {
        int r0g = row0 + wy * 32 + mt * 16 + gi;
#pragma unroll
        for (int nt = 0; nt < 8; nt++) {
            int cg = col0 + wx * 64 + nt * 8 + 2 * tg;
            if (SPLIT_OUT) {
                __nv_bfloat16 h0, l0, h1, l1;
                splitf(acc[mt][nt][0], h0, l0);
                splitf(acc[mt][nt][1], h1, l1);
                *(uint32_t*)&Ch[(size_t)r0g * 1024 + cg] = packbf(h0, h1);
                *(uint32_t*)&Cl[(size_t)r0g * 1024 + cg] = packbf(l0, l1);
                splitf(acc[mt][nt][2], h0, l0);
                splitf(acc[mt][nt][3], h1, l1);
                *(uint32_t*)&Ch[(size_t)(r0g + 8) * 1024 + cg] = packbf(h0, h1);
                *(uint32_t*)&Cl[(size_t)(r0g + 8) * 1024 + cg] = packbf(l0, l1);
            } else {
                *(float2*)&Cf[(size_t)r0g * 1024 + cg] =
                    make_float2(acc[mt][nt][0], acc[mt][nt][1]);
                *(float2*)&Cf[(size_t)(r0g + 8) * 1024 + cg] =
                    make_float2(acc[mt][nt][2], acc[mt][nt][3]);
            }
        }
    }
#undef GEMM_LOAD
}

__global__ void __launch_bounds__(256, 2)
proj_kernel()
{
    int z = blockIdx.z;
    const __nv_bfloat16* Bh = g_wh + ((size_t)z << 20);
    const __nv_bfloat16* Bl = g_wl + ((size_t)z << 20);
    __nv_bfloat16* Ch = (z == 0) ? g_qh : (z == 1) ? g_kh : g_vh;
    __nv_bfloat16* Cl = (z == 0) ? g_ql : (z == 1) ? g_kl : g_vl;
    gemm_core<true>(g_xh, g_xl, Bh, Bl, Ch, Cl, nullptr);
}

__global__ void __launch_bounds__(256, 2)
oproj_kernel(float* __restrict__ out)
{
    gemm_core<false>(g_ah, g_al, g_wh + ((size_t)3 << 20), g_wl + ((size_t)3 << 20),
                     nullptr, nullptr, out);
}

// ---------------------------------------------------------------------------
// Tensor-core flash attention (causal). CTA = 128 q rows, 8 warps x 16 rows,
// key tiles of 64, bf16 3-pass mma, register-resident P fragments.
// ---------------------------------------------------------------------------
#define AQH 0
#define AQL 18432
#define AKV0 36864
#define AKV_STAGE 36864
#define ATTN_SMEM (AKV0 + 2*AKV_STAGE)    // 110592

__global__ void __launch_bounds__(256, 2)
attn_kernel()
{
    extern __shared__ char smem[];
    const uint32_t sb = s2u(smem);
    const int tid  = threadIdx.x;
    const int lane = tid & 31;
    const int warp = tid >> 5;
    const int gi = lane >> 2, tg = lane & 3;

    const int qt = (int)gridDim.x - 1 - (int)blockIdx.x;   // big tiles first
    const int bh = blockIdx.y;
    const int b  = bh >> 4;
    const int h  = bh & 15;
    const size_t hoff = (size_t)b * SEQ * DMODEL + h * DK;

    const __nv_bfloat16* Qh = g_qh + hoff;
    const __nv_bfloat16* Ql = g_ql + hoff;
    const __nv_bfloat16* Kh = g_kh + hoff;
    const __nv_bfloat16* Kl = g_kl + hoff;
    const __nv_bfloat16* Vh = g_vh + hoff;
    const __nv_bfloat16* Vl = g_vl + hoff;

    const int row_base = qt * 128;
    const int ntiles = 2 * qt + 2;

    // prologue: Q tile (128x64 hi+lo)
#pragma unroll
    for (int c = 0; c < 4; c++) {
        int f = tid + c * 256;
        int row = f >> 3, seg = f & 7;
        size_t go = (size_t)(row_base + row) * 1024 + seg * 8;
        uint32_t so = (uint32_t)(row * 144 + seg * 16);
        CPA(sb + AQH + so, Qh + go);
        CPA(sb + AQL + so, Ql + go);
    }

#define LOAD_KV(jt, s)                                                     \
    {                                                                      \
        uint32_t d0 = sb + AKV0 + (uint32_t)(s) * AKV_STAGE;               \
        _Pragma("unroll")                                                  \
        for (int c = 0; c < 2; c++) {                                      \
            int f = tid + c * 256;                                         \
            int row = f >> 3, seg = f & 7;                                 \
            size_t go = (size_t)((jt) * 64 + row) * 1024 + seg * 8;        \
            uint32_t so = (uint32_t)(row * 144 + seg * 16);                \
            CPA(d0 + so,         Kh + go);                                 \
            CPA(d0 + 9216 + so,  Kl + go);                                 \
            CPA(d0 + 18432 + so, Vh + go);                                 \
            CPA(d0 + 27648 + so, Vl + go);                                 \
        }                                                                  \
    }

    LOAD_KV(0, 0);
    CPC();

    float o[8][4];
#pragma unroll
    for (int nt = 0; nt < 8; nt++)
#pragma unroll
        for (int r = 0; r < 4; r++) o[nt][r] = 0.0f;
    float m0 = -1e30f, m1 = -1e30f, l0v = 0.0f, l1v = 0.0f;

    const int r0 = warp * 16 + gi;     // local q row
    const int r1 = r0 + 8;
    const int grow0 = row_base + r0;
    const int grow1 = row_base + r1;

    // V ldmatrix lane addressing
    const int vrow_off = ((lane >> 3) & 1) * 8 + (lane & 7);
    const uint32_t vcolb = (uint32_t)((lane >> 4) * 16);

    const uint16_t* sQh = (const uint16_t*)(smem + AQH);
    const uint16_t* sQl = (const uint16_t*)(smem + AQL);

#pragma unroll 1
    for (int jt = 0; jt < ntiles; jt++) {
        const int s = jt & 1;
        __syncthreads();
        if (jt + 1 < ntiles) { LOAD_KV(jt + 1, s ^ 1); CPC(); CPW(1); }
        else                 { CPW(0); }
        __syncthreads();

        const uint16_t* sKh = (const uint16_t*)(smem + AKV0 + s * AKV_STAGE);
        const uint16_t* sKl = sKh + 4608;

        // ---- S = Q K^T (16 rows x 64 keys per warp) ----
        float sv[8][4];
#pragma unroll
        for (int nt = 0; nt < 8; nt++)
#pragma unroll
            for (int r = 0; r < 4; r++) sv[nt][r] = 0.0f;

#pragma unroll
        for (int ks = 0; ks < 4; ks++) {
            const int cb = ks * 16 + 2 * tg;
            uint32_t ah_[4], al_[4];
            ah_[0] = *(const uint32_t*)&sQh[r0 * 72 + cb];
            ah_[1] = *(const uint32_t*)&sQh[r1 * 72 + cb];
            ah_[2] = *(const uint32_t*)&sQh[r0 * 72 + cb + 8];
            ah_[3] = *(const uint32_t*)&sQh[r1 * 72 + cb + 8];
            al_[0] = *(const uint32_t*)&sQl[r0 * 72 + cb];
            al_[1] = *(const uint32_t*)&sQl[r1 * 72 + cb];
            al_[2] = *(const uint32_t*)&sQl[r0 * 72 + cb + 8];
            al_[3] = *(const uint32_t*)&sQl[r1 * 72 + cb + 8];
#pragma unroll
            for (int nt = 0; nt < 8; nt++) {
                int kr = nt * 8 + gi;
                uint32_t bh_[2], bl_[2];
                bh_[0] = *(const uint32_t*)&sKh[kr * 72 + cb];
                bh_[1] = *(const uint32_t*)&sKh[kr * 72 + cb + 8];
                bl_[0] = *(const uint32_t*)&sKl[kr * 72 + cb];
                bl_[1] = *(const uint32_t*)&sKl[kr * 72 + cb + 8];
                mma_bf16(sv[nt], ah_, bh_);
                mma_bf16(sv[nt], al_, bh_);
                mma_bf16(sv[nt], ah_, bl_);
            }
        }

        // ---- scale + causal mask ----
        const bool maskt = (jt >= 2 * qt);
#pragma unroll
        for (int nt = 0; nt < 8; nt++) {
            sv[nt][0] *= 0.125f; sv[nt][1] *= 0.125f;
            sv[nt][2] *= 0.125f; sv[nt][3] *= 0.125f;
            if (maskt) {
                int c0 = jt * 64 + nt * 8 + 2 * tg;
                if (c0     > grow0) sv[nt][0] = -1e30f;
                if (c0 + 1 > grow0) sv[nt][1] = -1e30f;
                if (c0     > grow1) sv[nt][2] = -1e30f;
                if (c0 + 1 > grow1) sv[nt][3] = -1e30f;
            }
        }

        // ---- online softmax (2 rows/thread, quad reduction) ----
        float mx0 = -1e30f, mx1 = -1e30f;
#pragma unroll
        for (int nt = 0; nt < 8; nt++) {
            mx0 = fmaxf(mx0, fmaxf(sv[nt][0], sv[nt][1]));
            mx1 = fmaxf(mx1, fmaxf(sv[nt][2], sv[nt][3]));
        }
        mx0 = fmaxf(mx0, __shfl_xor_sync(0xffffffffu, mx0, 1));
        mx0 = fmaxf(mx0, __shfl_xor_sync(0xffffffffu, mx0, 2));
        mx1 = fmaxf(mx1, __shfl_xor_sync(0xffffffffu, mx1, 1));
        mx1 = fmaxf(mx1, __shfl_xor_sync(0xffffffffu, mx1, 2));
        float nm0 = fmaxf(m0, mx0), nm1 = fmaxf(m1, mx1);
        float e0 = __expf(m0 - nm0), e1 = __expf(m1 - nm1);
        float rs0 = 0.0f, rs1 = 0.0f;
#pragma unroll
        for (int nt = 0; nt < 8; nt++) {
            sv[nt][0] = __expf(sv[nt][0] - nm0); rs0 += sv[nt][0];
            sv[nt][1] = __expf(sv[nt][1] - nm0); rs0 += sv[nt][1];
            sv[nt][2] = __expf(sv[nt][2] - nm1); rs1 += sv[nt][2];
            sv[nt][3] = __expf(sv[nt][3] - nm1); rs1 += sv[nt][3];
        }
        rs0 += __shfl_xor_sync(0xffffffffu, rs0, 1);
        rs0 += __shfl_xor_sync(0xffffffffu, rs0, 2);
        rs1 += __shfl_xor_sync(0xffffffffu, rs1, 1);
        rs1 += __shfl_xor_sync(0xffffffffu, rs1, 2);
        l0v = l0v * e0 + rs0;
        l1v = l1v * e1 + rs1;
        m0 = nm0; m1 = nm1;
#pragma unroll
        for (int nt = 0; nt < 8; nt++) {
            o[nt][0] *= e0; o[nt][1] *= e0;
            o[nt][2] *= e1; o[nt][3] *= e1;
        }

        // ---- O += P @ V (P fragments straight from S accumulators) ----
        const uint32_t vbase_h = sb + AKV0 + (uint32_t)s * AKV_STAGE + 18432;
        const uint32_t vbase_l = vbase_h + 9216;
#pragma unroll
        for (int ks = 0; ks < 4; ks++) {
            uint32_t ph[4], pl[4];
            {
                __nv_bfloat16 ha, la, hb, lb;
                splitf(sv[2*ks][0], ha, la); splitf(sv[2*ks][1], hb, lb);
                ph[0] = packbf(ha, hb); pl[0] = packbf(la, lb);
                splitf(sv[2*ks][2], ha, la); splitf(sv[2*ks][3], hb, lb);
                ph[1] = packbf(ha, hb); pl[1] = packbf(la, lb);
                splitf(sv[2*ks+1][0], ha, la); splitf(sv[2*ks+1][1], hb, lb);
                ph[2] = packbf(ha, hb); pl[2] = packbf(la, lb);
                splitf(sv[2*ks+1][2], ha, la); splitf(sv[2*ks+1][3], hb, lb);
                ph[3] = packbf(ha, hb); pl[3] = packbf(la, lb);
            }
            const uint32_t vrow = (uint32_t)(16 * ks + vrow_off);
#pragma unroll
            for (int p2 = 0; p2 < 4; p2++) {
                uint32_t off = vrow * 144 + (uint32_t)p2 * 32 + vcolb;
                uint32_t h0, h1, h2, h3, q0, q1, q2, q3;
                ldmx4t(h0, h1, h2, h3, vbase_h + off);
                ldmx4t(q0, q1, q2, q3, vbase_l + off);
                uint32_t bbh[2], bbl[2];
                bbh[0] = h0; bbh[1] = h1; bbl[0] = q0; bbl[1] = q1;
                mma_bf16(o[2*p2], ph, bbh);
                mma_bf16(o[2*p2], pl, bbh);
                mma_bf16(o[2*p2], ph, bbl);
                bbh[0] = h2; bbh[1] = h3; bbl[0] = q2; bbl[1] = q3;
                mma_bf16(o[2*p2+1], ph, bbh);
                mma_bf16(o[2*p2+1], pl, bbh);
                mma_bf16(o[2*p2+1], ph, bbl);
            }
        }
    }
#undef LOAD_KV

    // ---- epilogue: normalize, split, store bf16 hi/lo ----
    const float inv0 = 1.0f / l0v, inv1 = 1.0f / l1v;
    __nv_bfloat16* Oh = g_ah + hoff;
    __nv_bfloat16* Ol = g_al + hoff;
#pragma unroll
    for (int nt = 0; nt < 8; nt++) {
        int cg = nt * 8 + 2 * tg;
        __nv_bfloat16 ha, la, hb, lb;
        splitf(o[nt][0] * inv0, ha, la);
        splitf(o[nt][1] * inv0, hb, lb);
        *(uint32_t*)&Oh[(size_t)grow0 * 1024 + cg] = packbf(ha, hb);
        *(uint32_t*)&Ol[(size_t)grow0 * 1024 + cg] = packbf(la, lb);
        splitf(o[nt][2] * inv1, ha, la);
        splitf(o[nt][3] * inv1, hb, lb);
        *(uint32_t*)&Oh[(size_t)grow1 * 1024 + cg] = packbf(ha, hb);
        *(uint32_t*)&Ol[(size_t)grow1 * 1024 + cg] = packbf(la, lb);
    }
}

// ---------------------------------------------------------------------------
extern "C" void kernel_launch(void* const* d_in, const int* in_sizes, int n_in,
                              void* d_out, int out_size)
{
    (void)in_sizes; (void)n_in; (void)out_size;
    const float* x  = (const float*)d_in[0];
    const float* wq = (const float*)d_in[1];
    const float* wk = (const float*)d_in[2];
    const float* wv = (const float*)d_in[3];
    const float* wo = (const float*)d_in[4];
    float* out = (float*)d_out;

    cudaFuncSetAttribute(proj_kernel,
                         cudaFuncAttributeMaxDynamicSharedMemorySize, GEMM_SMEM);
    cudaFuncSetAttribute(oproj_kernel,
                         cudaFuncAttributeMaxDynamicSharedMemorySize, GEMM_SMEM);
    cudaFuncSetAttribute(attn_kernel,
                         cudaFuncAttributeMaxDynamicSharedMemorySize, ATTN_SMEM);

    split_kernel<<<8192, 256>>>(x, wq, wk, wv, wo);
    proj_kernel<<<dim3(8, 32, 3), 256, GEMM_SMEM>>>();
    attn_kernel<<<dim3(16, 32), 256, ATTN_SMEM>>>();
    oproj_kernel<<<dim3(8, 32), 256, GEMM_SMEM>>>(out);
}